// round 4
// baseline (speedup 1.0000x reference)
#include <cuda_runtime.h>
#include <cstdint>

// Problem shape (fixed for this problem instance)
#define B_  8
#define N_  256
#define T_  64
#define D_  512
#define NT_ (N_ * T_)          // 16384
#define ROWS_ (B_ * NT_)       // 131072

// __device__ scratch (no allocation allowed in kernel_launch)
__device__ int g_offsets[B_ * N_];   // exclusive prefix sum of length over n, per batch
__device__ int g_dsl[B_];            // doc_seq_len per batch
__device__ int g_src[B_ * NT_];      // src flat index (n*T + t) for each compacted slot j

// ---------------------------------------------------------------------------
// Kernel A: per-batch exclusive scan of length (N=256) + total
// ---------------------------------------------------------------------------
__global__ void scan_lengths(const int* __restrict__ length) {
    __shared__ int s[N_];
    int b = blockIdx.x;
    int n = threadIdx.x;
    int v = length[b * N_ + n];
    s[n] = v;
    __syncthreads();
    // Hillis-Steele inclusive scan
    #pragma unroll
    for (int off = 1; off < N_; off <<= 1) {
        int t = (n >= off) ? s[n - off] : 0;
        __syncthreads();
        s[n] += t;
        __syncthreads();
    }
    g_offsets[b * N_ + n] = s[n] - v;     // exclusive
    if (n == N_ - 1) g_dsl[b] = s[n];     // total = doc_seq_len
}

// ---------------------------------------------------------------------------
// Kernel B: scatter source indices. thread per (b,n,t).
// Compaction is dense: every j < dsl[b] gets exactly one writer.
// ---------------------------------------------------------------------------
__global__ void build_src(const int* __restrict__ length) {
    int idx = blockIdx.x * blockDim.x + threadIdx.x;  // [0, B*N*T)
    if (idx >= B_ * N_ * T_) return;
    int b = idx / (N_ * T_);
    int r = idx - b * (N_ * T_);
    int n = r / T_;
    int t = r - n * T_;
    if (t < length[b * N_ + n]) {
        int j = g_offsets[b * N_ + n] + t;
        g_src[b * NT_ + j] = n * T_ + t;
    }
}

// ---------------------------------------------------------------------------
// Kernel C: main gather+add, coalesced float4 writes.
// One block (128 threads) per output row of D=512 floats (128 float4).
// ---------------------------------------------------------------------------
__global__ __launch_bounds__(128) void write_new_x(
    const float* __restrict__ x,       // (B, NT, D)
    const float* __restrict__ x_gcn,   // (B, N, D)
    float* __restrict__ out_x)         // (B, NT, D)
{
    int row = blockIdx.x;              // [0, B*NT)
    int b = row >> 14;                 // / NT_
    int j = row & (NT_ - 1);
    int d = threadIdx.x;               // [0,128) float4 lanes

    const float4* gx = reinterpret_cast<const float4*>(
        x_gcn + ((size_t)(b * N_ + (j >> 6)) * D_));  // j / T_
    float4 g = gx[d];

    if (j < g_dsl[b]) {
        int src = g_src[row];
        const float4* xv = reinterpret_cast<const float4*>(
            x + (((size_t)b * NT_ + src) * D_));
        float4 v = xv[d];
        g.x += v.x; g.y += v.y; g.z += v.z; g.w += v.w;
    }
    reinterpret_cast<float4*>(out_x + (size_t)row * D_)[d] = g;
}

// ---------------------------------------------------------------------------
// Kernel D: small tails — new_mask, new_tag, doc_seq_len (all as float32)
// NOTE: tags input is int32 (JAX downcasts int64 without x64 enabled).
// ---------------------------------------------------------------------------
__global__ void write_tails(const int* __restrict__ tags,   // (B, NT) flat, int32
                            float* __restrict__ out_mask,
                            float* __restrict__ out_tag,
                            float* __restrict__ out_dsl)
{
    int idx = blockIdx.x * blockDim.x + threadIdx.x;   // [0, B*NT)
    if (idx >= ROWS_) return;
    int b = idx >> 14;
    int j = idx & (NT_ - 1);
    bool valid = (j < g_dsl[b]);
    out_mask[idx] = valid ? 1.0f : 0.0f;
    float tg = 0.0f;                                   // PAD_TAG = 0
    if (valid) {
        int src = g_src[idx];
        tg = (float)tags[b * NT_ + src];
    }
    out_tag[idx] = tg;
    if (idx < B_) out_dsl[idx] = (float)g_dsl[idx];
}

// ---------------------------------------------------------------------------
extern "C" void kernel_launch(void* const* d_in, const int* in_sizes, int n_in,
                              void* d_out, int out_size) {
    const float* x      = (const float*)d_in[0];      // (B,N,T,D)
    const float* x_gcn  = (const float*)d_in[1];      // (B,N,D)
    // d_in[2] = mask (unused: prefix mask fully determined by length)
    const int*   length = (const int*)d_in[3];        // (B,N)
    const int*   tags   = (const int*)d_in[4];        // (B,N,T) int32 (JAX downcast)

    float* out = (float*)d_out;
    // Output layout: [new_x | new_mask | doc_seq_len | new_tag] flattened fp32
    const size_t nx_elems   = (size_t)ROWS_ * D_;         // 67,108,864
    float* out_x    = out;
    float* out_mask = out + nx_elems;
    float* out_dsl  = out_mask + ROWS_;
    float* out_tag  = out_dsl + B_;

    scan_lengths<<<B_, N_>>>(length);
    build_src<<<(B_ * N_ * T_ + 255) / 256, 256>>>(length);
    write_new_x<<<ROWS_, 128>>>(x, x_gcn, out_x);

    // Only write the tails if the output buffer actually contains them
    if ((size_t)out_size >= nx_elems + 2 * ROWS_ + B_) {
        write_tails<<<(ROWS_ + 255) / 256, 256>>>(tags, out_mask, out_tag, out_dsl);
    }
}

// round 5
// speedup vs baseline: 1.1565x; 1.1565x over previous
#include <cuda_runtime.h>
#include <cstdint>

// Problem shape (fixed for this problem instance)
#define B_  8
#define N_  256
#define T_  64
#define D_  512
#define NT_ (N_ * T_)          // 16384
#define ROWS_ (B_ * NT_)       // 131072

// __device__ scratch (no allocation allowed in kernel_launch)
__device__ int g_dsl[B_];            // doc_seq_len per batch
__device__ int g_src[B_ * NT_];      // src flat index (n*T + t) for each compacted slot j

// ---------------------------------------------------------------------------
// Kernel 1: per-batch scan of length + src-index scatter, fused.
// One block per batch (B=8), 256 threads (= N).
// ---------------------------------------------------------------------------
__global__ __launch_bounds__(N_) void setup_indices(const int* __restrict__ length) {
    __shared__ int s[N_];
    int b = blockIdx.x;
    int n = threadIdx.x;
    int v = length[b * N_ + n];
    s[n] = v;
    __syncthreads();
    // Hillis-Steele inclusive scan over N=256
    #pragma unroll
    for (int off = 1; off < N_; off <<= 1) {
        int t = (n >= off) ? s[n - off] : 0;
        __syncthreads();
        s[n] += t;
        __syncthreads();
    }
    int offset = s[n] - v;               // exclusive prefix
    if (n == N_ - 1) g_dsl[b] = s[n];    // total = doc_seq_len

    // Each thread writes its segment's compacted src indices
    int* dst = g_src + b * NT_ + offset;
    int base = n * T_;
    for (int t = 0; t < v; t++) dst[t] = base + t;
}

// ---------------------------------------------------------------------------
// Kernel 2: everything else, fused. One 256-thread block per output segment
// (b, nOut): 64 rows of D=512 floats sharing one x_gcn row (kept in regs).
// Two rows processed per loop iteration (half = tid>>7).
// ---------------------------------------------------------------------------
__global__ __launch_bounds__(256) void write_all(
    const float* __restrict__ x,       // (B, NT, D)
    const float* __restrict__ x_gcn,   // (B, N, D)
    const int*   __restrict__ tags,    // (B, NT) int32
    float* __restrict__ out_x,         // (B, NT, D)
    float* __restrict__ out_mask,      // (B, NT)
    float* __restrict__ out_tag,       // (B, NT)
    float* __restrict__ out_dsl,       // (B,)
    int do_tails)
{
    int seg  = blockIdx.x;             // [0, B*N)
    int b    = seg >> 8;               // / N_
    int nOut = seg & (N_ - 1);
    int lane = threadIdx.x & 127;      // float4 lane within a row
    int half = threadIdx.x >> 7;       // 0/1: two rows in flight

    // gcn row for this output segment: loaded ONCE, reused for all 64 rows
    const float4 g = reinterpret_cast<const float4*>(
        x_gcn + ((size_t)(b * N_ + nOut) * D_))[lane];

    int dsl   = g_dsl[b];
    int jbase = nOut * T_;

    // Stage the segment's 64 src indices in smem (values beyond dsl are
    // stale scratch but never dereferenced — guarded by j < dsl).
    __shared__ int s_src[T_];
    if (threadIdx.x < T_)
        s_src[threadIdx.x] = g_src[b * NT_ + jbase + threadIdx.x];
    __syncthreads();

    const float* xb   = x     + (size_t)b * NT_ * D_;
    float*       oxb  = out_x + (size_t)b * NT_ * D_;

    #pragma unroll 4
    for (int r = half; r < T_; r += 2) {
        int j = jbase + r;
        float4 o = g;
        bool valid = (j < dsl);
        if (valid) {
            int src = s_src[r];
            float4 v = reinterpret_cast<const float4*>(xb + (size_t)src * D_)[lane];
            o.x += v.x; o.y += v.y; o.z += v.z; o.w += v.w;
        }
        reinterpret_cast<float4*>(oxb + (size_t)j * D_)[lane] = o;

        if (do_tails && lane == 0) {
            int fi = b * NT_ + j;
            out_mask[fi] = valid ? 1.0f : 0.0f;
            out_tag[fi]  = valid ? (float)tags[b * NT_ + s_src[r]] : 0.0f;
        }
    }

    if (do_tails && seg < B_ && threadIdx.x == 0)
        out_dsl[seg] = (float)g_dsl[seg];
}

// ---------------------------------------------------------------------------
extern "C" void kernel_launch(void* const* d_in, const int* in_sizes, int n_in,
                              void* d_out, int out_size) {
    const float* x      = (const float*)d_in[0];      // (B,N,T,D)
    const float* x_gcn  = (const float*)d_in[1];      // (B,N,D)
    // d_in[2] = mask (unused: prefix mask fully determined by length)
    const int*   length = (const int*)d_in[3];        // (B,N)
    const int*   tags   = (const int*)d_in[4];        // (B,N,T) int32 (JAX downcast)

    float* out = (float*)d_out;
    // Output layout: [new_x | new_mask | doc_seq_len | new_tag] flattened fp32
    const size_t nx_elems = (size_t)ROWS_ * D_;       // 67,108,864
    float* out_x    = out;
    float* out_mask = out + nx_elems;
    float* out_dsl  = out_mask + ROWS_;
    float* out_tag  = out_dsl + B_;

    int do_tails = ((size_t)out_size >= nx_elems + 2 * ROWS_ + B_) ? 1 : 0;

    setup_indices<<<B_, N_>>>(length);
    write_all<<<B_ * N_, 256>>>(x, x_gcn, tags, out_x, out_mask, out_tag,
                                out_dsl, do_tails);
}

// round 6
// speedup vs baseline: 1.2433x; 1.0751x over previous
#include <cuda_runtime.h>
#include <cstdint>

// Problem shape (fixed for this problem instance)
#define B_  8
#define N_  256
#define T_  64
#define D_  512
#define NT_ (N_ * T_)          // 16384
#define ROWS_ (B_ * NT_)       // 131072

// __device__ scratch (no allocation allowed in kernel_launch)
__device__ int g_dsl[B_];            // doc_seq_len per batch
__device__ int g_off[B_ * N_];       // exclusive prefix sum of length over n

// ---------------------------------------------------------------------------
// Kernel 1: per-batch exclusive scan of length. One block per batch.
// ---------------------------------------------------------------------------
__global__ __launch_bounds__(N_) void setup_scan(const int* __restrict__ length) {
    __shared__ int s[N_];
    int b = blockIdx.x;
    int n = threadIdx.x;
    int v = length[b * N_ + n];
    s[n] = v;
    __syncthreads();
    #pragma unroll
    for (int off = 1; off < N_; off <<= 1) {
        int t = (n >= off) ? s[n - off] : 0;
        __syncthreads();
        s[n] += t;
        __syncthreads();
    }
    g_off[b * N_ + n] = s[n] - v;        // exclusive prefix
    if (n == N_ - 1) g_dsl[b] = s[n];    // total
}

// ---------------------------------------------------------------------------
// Kernel 2: fused gather+add+tails. One 256-thread block per output segment
// (b, nOut): 64 rows of D=512 floats sharing one x_gcn row (kept in regs).
// Source row index resolved by binary search over the batch's offsets.
// ---------------------------------------------------------------------------
__global__ __launch_bounds__(256) void write_all(
    const float* __restrict__ x,       // (B, NT, D)
    const float* __restrict__ x_gcn,   // (B, N, D)
    const int*   __restrict__ tags,    // (B, NT) int32
    float* __restrict__ out_x,         // (B, NT, D)
    float* __restrict__ out_mask,      // (B, NT)
    float* __restrict__ out_tag,       // (B, NT)
    float* __restrict__ out_dsl,       // (B,)
    int do_tails)
{
    int seg  = blockIdx.x;             // [0, B*N)
    int b    = seg >> 8;               // / N_
    int nOut = seg & (N_ - 1);
    int lane = threadIdx.x & 127;      // float4 lane within a row
    int half = threadIdx.x >> 7;       // 0/1: two rows in flight

    __shared__ int s_off[N_];
    __shared__ int s_src[T_];

    // Stage this batch's offsets (L2-resident, 1KB)
    s_off[threadIdx.x & (N_ - 1)] = g_off[b * N_ + (threadIdx.x & (N_ - 1))];

    // gcn row for this output segment: loaded ONCE, reused for all 64 rows
    const float4 g = reinterpret_cast<const float4*>(
        x_gcn + ((size_t)(b * N_ + nOut) * D_))[lane];

    int dsl   = g_dsl[b];
    int jbase = nOut * T_;
    __syncthreads();

    // 64 threads resolve src for the block's 64 output rows via binary search
    if (threadIdx.x < T_) {
        int j = jbase + threadIdx.x;
        if (j < dsl) {
            int lo = 0, hi = N_ - 1;
            #pragma unroll
            for (int it = 0; it < 8; it++) {       // log2(256)
                int mid = (lo + hi + 1) >> 1;
                if (s_off[mid] <= j) lo = mid; else hi = mid - 1;
            }
            s_src[threadIdx.x] = lo * T_ + (j - s_off[lo]);
        }
    }
    __syncthreads();

    const float* xb  = x     + (size_t)b * NT_ * D_;
    float*       oxb = out_x + (size_t)b * NT_ * D_;

    #pragma unroll 4
    for (int r = half; r < T_; r += 2) {
        int j = jbase + r;
        float4 o = g;
        bool valid = (j < dsl);
        if (valid) {
            int src = s_src[r];
            const float4* vp = reinterpret_cast<const float4*>(
                xb + (size_t)src * D_) + lane;
            float4 v = __ldcs(vp);                 // read-once stream
            o.x += v.x; o.y += v.y; o.z += v.z; o.w += v.w;
        }
        __stcs(reinterpret_cast<float4*>(oxb + (size_t)j * D_) + lane, o);

        if (do_tails && lane == 0) {
            int fi = b * NT_ + j;
            out_mask[fi] = valid ? 1.0f : 0.0f;
            out_tag[fi]  = valid ? (float)tags[b * NT_ + s_src[r]] : 0.0f;
        }
    }

    if (do_tails && seg < B_ && threadIdx.x == 0)
        out_dsl[seg] = (float)g_dsl[seg];
}

// ---------------------------------------------------------------------------
extern "C" void kernel_launch(void* const* d_in, const int* in_sizes, int n_in,
                              void* d_out, int out_size) {
    const float* x      = (const float*)d_in[0];      // (B,N,T,D)
    const float* x_gcn  = (const float*)d_in[1];      // (B,N,D)
    // d_in[2] = mask (unused: prefix mask fully determined by length)
    const int*   length = (const int*)d_in[3];        // (B,N)
    const int*   tags   = (const int*)d_in[4];        // (B,N,T) int32 (JAX downcast)

    float* out = (float*)d_out;
    // Output layout: [new_x | new_mask | doc_seq_len | new_tag] flattened fp32
    const size_t nx_elems = (size_t)ROWS_ * D_;       // 67,108,864
    float* out_x    = out;
    float* out_mask = out + nx_elems;
    float* out_dsl  = out_mask + ROWS_;
    float* out_tag  = out_dsl + B_;

    int do_tails = ((size_t)out_size >= nx_elems + 2 * ROWS_ + B_) ? 1 : 0;

    setup_scan<<<B_, N_>>>(length);
    write_all<<<B_ * N_, 256>>>(x, x_gcn, tags, out_x, out_mask, out_tag,
                                out_dsl, do_tails);
}

// round 9
// speedup vs baseline: 1.3098x; 1.0535x over previous
#include <cuda_runtime.h>
#include <cstdint>

// Problem shape (fixed for this problem instance)
#define B_  8
#define N_  256
#define T_  64
#define D_  512
#define NT_ (N_ * T_)          // 16384
#define ROWS_ (B_ * NT_)       // 131072

// ---------------------------------------------------------------------------
// Single fused kernel. One 256-thread block per output segment (b, nOut).
// Each block:
//   1. re-runs the per-batch scan of length[] in smem (1KB, L2-resident)
//   2. resolves the 64 src row indices via smem binary search
//   3. streams 64 rows of D=512 floats: out = x_gcn_row + (valid ? x[src] : 0)
//      with 4-deep batched loads for MLP
//   4. lane 0 writes mask/tag tails; nOut==0 block writes doc_seq_len[b]
// ---------------------------------------------------------------------------
__global__ __launch_bounds__(256) void write_all(
    const float* __restrict__ x,       // (B, NT, D)
    const float* __restrict__ x_gcn,   // (B, N, D)
    const int*   __restrict__ length,  // (B, N)
    const int*   __restrict__ tags,    // (B, NT) int32
    float* __restrict__ out_x,         // (B, NT, D)
    float* __restrict__ out_mask,      // (B, NT)
    float* __restrict__ out_tag,       // (B, NT)
    float* __restrict__ out_dsl,       // (B,)
    int do_tails)
{
    int seg  = blockIdx.x;             // [0, B*N)
    int b    = seg >> 8;               // / N_
    int nOut = seg & (N_ - 1);
    int tid  = threadIdx.x;
    int lane = tid & 127;              // float4 lane within a row
    int half = tid >> 7;               // 0/1: two rows interleaved

    __shared__ int s_off[N_];          // scan scratch -> exclusive offsets
    __shared__ int s_src[T_];
    __shared__ int sh_dsl;

    // --- per-block scan of this batch's lengths (256 threads = N) ---
    int v = length[b * N_ + tid];
    s_off[tid] = v;
    __syncthreads();
    #pragma unroll
    for (int off = 1; off < N_; off <<= 1) {
        int t = (tid >= off) ? s_off[tid - off] : 0;
        __syncthreads();
        s_off[tid] += t;
        __syncthreads();
    }
    int incl = s_off[tid];
    if (tid == N_ - 1) sh_dsl = incl;  // doc_seq_len of this batch
    __syncthreads();
    s_off[tid] = incl - v;             // convert to exclusive in-place
    __syncthreads();

    int dsl   = sh_dsl;
    int jbase = nOut * T_;

    // --- 64 threads resolve src rows via binary search over offsets ---
    if (tid < T_) {
        int j = jbase + tid;
        if (j < dsl) {
            int lo = 0, hi = N_ - 1;
            #pragma unroll
            for (int it = 0; it < 8; it++) {       // log2(256)
                int mid = (lo + hi + 1) >> 1;
                if (s_off[mid] <= j) lo = mid; else hi = mid - 1;
            }
            s_src[tid] = lo * T_ + (j - s_off[lo]);
        }
    }

    // gcn row for this segment: loaded once, reused for all 64 rows
    const float4 g = reinterpret_cast<const float4*>(
        x_gcn + ((size_t)(b * N_ + nOut) * D_))[lane];
    __syncthreads();

    const float* xb  = x     + (size_t)b * NT_ * D_;
    float*       oxb = out_x + (size_t)b * NT_ * D_;

    // --- main stream: 32 rows/thread, chunks of 4 batched loads ---
    #pragma unroll
    for (int c = 0; c < 8; c++) {
        int r0 = c * 8 + half;
        float4 vv[4];
        bool   va[4];
        int    sr[4];
        #pragma unroll
        for (int k = 0; k < 4; k++) {
            int r = r0 + 2 * k;
            int j = jbase + r;
            va[k] = (j < dsl);
            sr[k] = va[k] ? s_src[r] : 0;
            if (va[k])
                vv[k] = reinterpret_cast<const float4*>(
                    xb + (size_t)sr[k] * D_)[lane];
        }
        #pragma unroll
        for (int k = 0; k < 4; k++) {
            int r = r0 + 2 * k;
            int j = jbase + r;
            float4 o = g;
            if (va[k]) {
                o.x += vv[k].x; o.y += vv[k].y;
                o.z += vv[k].z; o.w += vv[k].w;
            }
            reinterpret_cast<float4*>(oxb + (size_t)j * D_)[lane] = o;

            if (do_tails && lane == 0) {
                int fi = b * NT_ + j;
                out_mask[fi] = va[k] ? 1.0f : 0.0f;
                out_tag[fi]  = va[k] ? (float)tags[b * NT_ + sr[k]] : 0.0f;
            }
        }
    }

    // FIX: the nOut==0 block of EACH batch writes its own dsl
    // (previously blocks seg<8, all batch 0, wrote out_dsl[0..7])
    if (do_tails && nOut == 0 && tid == 0)
        out_dsl[b] = (float)dsl;
}

// ---------------------------------------------------------------------------
extern "C" void kernel_launch(void* const* d_in, const int* in_sizes, int n_in,
                              void* d_out, int out_size) {
    const float* x      = (const float*)d_in[0];      // (B,N,T,D)
    const float* x_gcn  = (const float*)d_in[1];      // (B,N,D)
    // d_in[2] = mask (unused: prefix mask fully determined by length)
    const int*   length = (const int*)d_in[3];        // (B,N)
    const int*   tags   = (const int*)d_in[4];        // (B,N,T) int32 (JAX downcast)

    float* out = (float*)d_out;
    // Output layout: [new_x | new_mask | doc_seq_len | new_tag] flattened fp32
    const size_t nx_elems = (size_t)ROWS_ * D_;       // 67,108,864
    float* out_x    = out;
    float* out_mask = out + nx_elems;
    float* out_dsl  = out_mask + ROWS_;
    float* out_tag  = out_dsl + B_;

    int do_tails = ((size_t)out_size >= nx_elems + 2 * ROWS_ + B_) ? 1 : 0;

    write_all<<<B_ * N_, 256>>>(x, x_gcn, length, tags,
                                out_x, out_mask, out_tag, out_dsl, do_tails);
}

// round 10
// speedup vs baseline: 1.3115x; 1.0013x over previous
#include <cuda_runtime.h>
#include <cstdint>

// Problem shape (fixed for this problem instance)
#define B_  8
#define N_  256
#define T_  64
#define D_  512
#define NT_ (N_ * T_)          // 16384
#define ROWS_ (B_ * NT_)       // 131072

// ---------------------------------------------------------------------------
// Single fused kernel. One 256-thread block per output segment (b, nOut).
//   1. per-block scan of length[] in smem (L2-resident input, 1KB)
//   2. binary-search src row indices into smem
//   3. three specialized paths: fully-valid / fully-invalid / boundary
// __launch_bounds__(256,6) caps regs at ~42 -> occ ~75% with MLP=4 batching.
// ---------------------------------------------------------------------------
__global__ __launch_bounds__(256, 6) void write_all(
    const float* __restrict__ x,       // (B, NT, D)
    const float* __restrict__ x_gcn,   // (B, N, D)
    const int*   __restrict__ length,  // (B, N)
    const int*   __restrict__ tags,    // (B, NT) int32
    float* __restrict__ out_x,         // (B, NT, D)
    float* __restrict__ out_mask,      // (B, NT)
    float* __restrict__ out_tag,       // (B, NT)
    float* __restrict__ out_dsl,       // (B,)
    int do_tails)
{
    int seg  = blockIdx.x;             // [0, B*N)
    int b    = seg >> 8;               // / N_
    int nOut = seg & (N_ - 1);
    int tid  = threadIdx.x;
    int lane = tid & 127;              // float4 lane within a row
    int half = tid >> 7;               // 0/1: two rows interleaved

    __shared__ int s_off[N_];          // scan scratch -> exclusive offsets
    __shared__ int s_src[T_];
    __shared__ int sh_dsl;

    // --- per-block scan of this batch's lengths (256 threads = N) ---
    int v = length[b * N_ + tid];
    s_off[tid] = v;
    __syncthreads();
    #pragma unroll
    for (int off = 1; off < N_; off <<= 1) {
        int t = (tid >= off) ? s_off[tid - off] : 0;
        __syncthreads();
        s_off[tid] += t;
        __syncthreads();
    }
    int incl = s_off[tid];
    if (tid == N_ - 1) sh_dsl = incl;  // doc_seq_len of this batch
    __syncthreads();
    s_off[tid] = incl - v;             // convert to exclusive in-place
    __syncthreads();

    int dsl   = sh_dsl;
    int jbase = nOut * T_;

    // --- 64 threads resolve src rows via binary search over offsets ---
    if (tid < T_) {
        int j = jbase + tid;
        if (j < dsl) {
            int lo = 0, hi = N_ - 1;
            #pragma unroll
            for (int it = 0; it < 8; it++) {       // log2(256)
                int mid = (lo + hi + 1) >> 1;
                if (s_off[mid] <= j) lo = mid; else hi = mid - 1;
            }
            s_src[tid] = lo * T_ + (j - s_off[lo]);
        }
    }

    // gcn row for this segment: loaded once, reused for all 64 rows
    const float4 g = reinterpret_cast<const float4*>(
        x_gcn + ((size_t)(b * N_ + nOut) * D_))[lane];
    __syncthreads();

    const float* xb  = x     + (size_t)b * NT_ * D_;
    float*       oxb = out_x + (size_t)b * NT_ * D_;

    if (jbase + T_ <= dsl) {
        // ================= fully valid: clean 4-deep stream =================
        #pragma unroll
        for (int c = 0; c < 8; c++) {
            int r0 = c * 8 + half;
            float4 vv[4];
            #pragma unroll
            for (int k = 0; k < 4; k++)
                vv[k] = reinterpret_cast<const float4*>(
                    xb + (size_t)s_src[r0 + 2 * k] * D_)[lane];
            #pragma unroll
            for (int k = 0; k < 4; k++) {
                int r = r0 + 2 * k;
                float4 o;
                o.x = g.x + vv[k].x; o.y = g.y + vv[k].y;
                o.z = g.z + vv[k].z; o.w = g.w + vv[k].w;
                reinterpret_cast<float4*>(oxb + (size_t)(jbase + r) * D_)[lane] = o;
                if (do_tails && lane == 0) {
                    int fi = b * NT_ + jbase + r;
                    out_mask[fi] = 1.0f;
                    out_tag[fi]  = (float)tags[b * NT_ + s_src[r]];
                }
            }
        }
    } else if (jbase >= dsl) {
        // ================= fully invalid: pure gcn write ====================
        #pragma unroll
        for (int r = half; r < T_; r += 2) {
            reinterpret_cast<float4*>(oxb + (size_t)(jbase + r) * D_)[lane] = g;
            if (do_tails && lane == 0) {
                int fi = b * NT_ + jbase + r;
                out_mask[fi] = 0.0f;
                out_tag[fi]  = 0.0f;
            }
        }
    } else {
        // ================= boundary (1 block per batch) =====================
        for (int r = half; r < T_; r += 2) {
            int j = jbase + r;
            bool valid = (j < dsl);
            float4 o = g;
            int src = valid ? s_src[r] : 0;
            if (valid) {
                float4 vv = reinterpret_cast<const float4*>(
                    xb + (size_t)src * D_)[lane];
                o.x += vv.x; o.y += vv.y; o.z += vv.z; o.w += vv.w;
            }
            reinterpret_cast<float4*>(oxb + (size_t)j * D_)[lane] = o;
            if (do_tails && lane == 0) {
                int fi = b * NT_ + j;
                out_mask[fi] = valid ? 1.0f : 0.0f;
                out_tag[fi]  = valid ? (float)tags[b * NT_ + src] : 0.0f;
            }
        }
    }

    // nOut==0 block of EACH batch writes its own dsl
    if (do_tails && nOut == 0 && tid == 0)
        out_dsl[b] = (float)dsl;
}

// ---------------------------------------------------------------------------
extern "C" void kernel_launch(void* const* d_in, const int* in_sizes, int n_in,
                              void* d_out, int out_size) {
    const float* x      = (const float*)d_in[0];      // (B,N,T,D)
    const float* x_gcn  = (const float*)d_in[1];      // (B,N,D)
    // d_in[2] = mask (unused: prefix mask fully determined by length)
    const int*   length = (const int*)d_in[3];        // (B,N)
    const int*   tags   = (const int*)d_in[4];        // (B,N,T) int32 (JAX downcast)

    float* out = (float*)d_out;
    // Output layout: [new_x | new_mask | doc_seq_len | new_tag] flattened fp32
    const size_t nx_elems = (size_t)ROWS_ * D_;       // 67,108,864
    float* out_x    = out;
    float* out_mask = out + nx_elems;
    float* out_dsl  = out_mask + ROWS_;
    float* out_tag  = out_dsl + B_;

    int do_tails = ((size_t)out_size >= nx_elems + 2 * ROWS_ + B_) ? 1 : 0;

    write_all<<<B_ * N_, 256>>>(x, x_gcn, length, tags,
                                out_x, out_mask, out_tag, out_dsl, do_tails);
}